// round 1
// baseline (speedup 1.0000x reference)
#include <cuda_runtime.h>
#include <cstdint>
#include <cstddef>

#define TOKENS (2*128*128)

// ---------------- scratch (device globals; no allocation allowed) ----------
__device__ float g_feat[TOKENS*60];
__device__ float g_qkv [TOKENS*180];
__device__ float g_attn[TOKENS*60];
__device__ float g_mlp [TOKENS*120];

// ---------------- FFMA-only exp (avoids MUFU bottleneck) -------------------
__device__ __forceinline__ float fexp(float x){
  x = fminf(fmaxf(x, -87.0f), 87.0f);
  float t  = x * 1.4426950408889634f;       // x * log2(e)
  float kf = t + 12582912.0f;               // 1.5 * 2^23 round-to-nearest
  float i  = kf - 12582912.0f;              // integer part (exact float)
  float f  = t - i;                         // frac in [-0.5, 0.5]
  float p  = 1.3333558e-3f;                 // 2^f Taylor deg-5
  p = fmaf(p, f, 9.6181291e-3f);
  p = fmaf(p, f, 5.5504109e-2f);
  p = fmaf(p, f, 2.4022651e-1f);
  p = fmaf(p, f, 6.9314718e-1f);
  p = fmaf(p, f, 1.0f);
  int e = (int)i;
  return p * __int_as_float((e + 127) << 23);
}

// Newton reciprocal (avoids MUFU RCP in 141M swish evals)
__device__ __forceinline__ float frcp_nr(float y){
  float r = __int_as_float(0x7EF311C3u - __float_as_int(y));
  r = r * (2.0f - y * r);
  r = r * (2.0f - y * r);
  return r;
}

// ---------------- first conv: x[2,3,128,128] -> feat[2,128,128,60] ---------
__global__ __launch_bounds__(256) void conv_in_kernel(
    const float* __restrict__ x, const float* __restrict__ w,
    const float* __restrict__ b, float* __restrict__ feat)
{
  int idx = blockIdx.x*256 + threadIdx.x;
  if (idx >= TOKENS*60) return;
  int co = idx % 60;
  int t  = idx / 60;
  int wq = t & 127;
  int hq = (t >> 7) & 127;
  int bq = t >> 14;
  float s = b[co];
  #pragma unroll
  for (int kh = 0; kh < 3; kh++){
    int hh = hq + kh - 1;
    if ((unsigned)hh > 127u) continue;
    #pragma unroll
    for (int kw = 0; kw < 3; kw++){
      int wwq = wq + kw - 1;
      if ((unsigned)wwq > 127u) continue;
      const float* xp = x + (size_t)((bq*3)*128 + hh)*128 + wwq;
      #pragma unroll
      for (int ci = 0; ci < 3; ci++)
        s = fmaf(xp[(size_t)ci*128*128], w[((co*3+ci)*3+kh)*3+kw], s);
    }
  }
  feat[idx] = s;
}

// ---------------- generic small-K GEMM with fused LN / swish / residual ----
// X:[M,K]  W:[K,Nfull]  Out:[M,Nfull]; block tile 64(M) x 60(N); 256 threads,
// thread tile 4x4.  K in {60,120}, processed in 60-chunks.
template<int K, bool DOLN, bool SWISH, bool RESID>
__global__ __launch_bounds__(256) void gemm_kernel(
    const float* __restrict__ X, const float* __restrict__ W,
    const float* __restrict__ bias,
    const float* __restrict__ lng, const float* __restrict__ lnb,
    float* __restrict__ Out, int Nfull)
{
  static_assert(!(DOLN && K != 60), "LN fusion only for K=60");
  __shared__ float Xs[64][61];   // +1 pad: conflict-free column reads
  __shared__ float Ws[60][64];   // row k, padded to 64 cols for float4
  const int m0  = blockIdx.x * 64;
  const int n0  = blockIdx.y * 60;
  const int tid = threadIdx.x;
  const int tx  = tid & 15, ty = tid >> 4;

  float acc[4][4];
  #pragma unroll
  for (int i = 0; i < 4; i++)
    #pragma unroll
    for (int j = 0; j < 4; j++) acc[i][j] = 0.f;

  for (int k0 = 0; k0 < K; k0 += 60){
    for (int idx = tid; idx < 64*60; idx += 256){
      int rr = idx / 60, cc = idx - rr*60;
      Xs[rr][cc] = X[(size_t)(m0+rr)*K + k0 + cc];
    }
    for (int idx = tid; idx < 60*64; idx += 256){
      int rr = idx >> 6, cc = idx & 63;
      Ws[rr][cc] = (cc < 60) ? W[(size_t)(k0+rr)*Nfull + n0 + cc] : 0.f;
    }
    __syncthreads();
    if (DOLN){
      if (tid < 64){
        float mu = 0.f;
        #pragma unroll
        for (int c = 0; c < 60; c++) mu += Xs[tid][c];
        mu *= (1.0f/60.0f);
        float var = 0.f;
        #pragma unroll
        for (int c = 0; c < 60; c++){ float d = Xs[tid][c]-mu; var = fmaf(d,d,var); }
        float rs = rsqrtf(var*(1.0f/60.0f) + 1e-5f);
        #pragma unroll
        for (int c = 0; c < 60; c++)
          Xs[tid][c] = (Xs[tid][c]-mu)*rs*lng[c] + lnb[c];
      }
      __syncthreads();
    }
    #pragma unroll 10
    for (int k = 0; k < 60; k++){
      float4 bq = *reinterpret_cast<const float4*>(&Ws[k][tx*4]);
      float a0 = Xs[ty*4+0][k];
      float a1 = Xs[ty*4+1][k];
      float a2 = Xs[ty*4+2][k];
      float a3 = Xs[ty*4+3][k];
      acc[0][0]=fmaf(a0,bq.x,acc[0][0]); acc[0][1]=fmaf(a0,bq.y,acc[0][1]);
      acc[0][2]=fmaf(a0,bq.z,acc[0][2]); acc[0][3]=fmaf(a0,bq.w,acc[0][3]);
      acc[1][0]=fmaf(a1,bq.x,acc[1][0]); acc[1][1]=fmaf(a1,bq.y,acc[1][1]);
      acc[1][2]=fmaf(a1,bq.z,acc[1][2]); acc[1][3]=fmaf(a1,bq.w,acc[1][3]);
      acc[2][0]=fmaf(a2,bq.x,acc[2][0]); acc[2][1]=fmaf(a2,bq.y,acc[2][1]);
      acc[2][2]=fmaf(a2,bq.z,acc[2][2]); acc[2][3]=fmaf(a2,bq.w,acc[2][3]);
      acc[3][0]=fmaf(a3,bq.x,acc[3][0]); acc[3][1]=fmaf(a3,bq.y,acc[3][1]);
      acc[3][2]=fmaf(a3,bq.z,acc[3][2]); acc[3][3]=fmaf(a3,bq.w,acc[3][3]);
    }
    __syncthreads();
  }

  #pragma unroll
  for (int i = 0; i < 4; i++){
    int mrow = m0 + ty*4 + i;
    #pragma unroll
    for (int j = 0; j < 4; j++){
      int nn = tx*4 + j;
      if (nn < 60){
        int ncol = n0 + nn;
        float v = acc[i][j] + bias[ncol];
        if (SWISH){
          float e = fexp(-v);
          v = v * frcp_nr(1.0f + e);
        }
        size_t o = (size_t)mrow * Nfull + ncol;
        if (RESID) Out[o] += v; else Out[o] = v;
      }
    }
  }
}

// ---------------- windowed attention (flash-style, one query per thread) ---
// qkv:[B,H,W,180] (q:0..59, k:60..119, v:120..179; channel = head*20+d)
// out:[B,H,W,60] scattered back through the roll.
__global__ __launch_bounds__(256) void attn_kernel(
    const float* __restrict__ qkv, float* __restrict__ out,
    int wh, int ww, int sh, int sw, int masked)
{
  __shared__ float ks[256][20];
  __shared__ float vs[256][20];
  __shared__ int   rid[256];
  const int win  = blockIdx.x;     // 0..127 (B * nH * nW)
  const int head = blockIdx.y;     // 0..2
  const int nWc = 128 / ww;
  const int nHc = 128 / wh;
  const int b   = win / (nHc*nWc);
  const int rem = win % (nHc*nWc);
  const int ih  = rem / nWc, iw = rem % nWc;
  const int n   = threadIdx.x;
  const int r   = n / ww, col = n % ww;
  const int h   = ih*wh + r, w = iw*ww + col;           // rolled-grid coords
  const int gh  = (h + sh) & 127, gw = (w + sw) & 127;  // original coords
  const int gidx = (b*128 + gh)*128 + gw;
  const float* bp = qkv + (size_t)gidx*180 + head*20;

  float q[20];
  #pragma unroll
  for (int d = 0; d < 20; d++){
    q[d]     = bp[d];
    ks[n][d] = bp[60+d];
    vs[n][d] = bp[120+d];
  }
  // shifted-window region id on rolled grid (Swin mask, computed on the fly)
  int rh = (h < 128-wh) ? 0 : ((h < 128-sh) ? 1 : 2);
  int rw = (w < 128-ww) ? 0 : ((w < 128-sw) ? 1 : 2);
  rid[n] = rh*3 + rw;
  __syncthreads();

  const int myrid = rid[n];
  float m = -3.0e38f, l = 0.f;
  float acc[20];
  #pragma unroll
  for (int d = 0; d < 20; d++) acc[d] = 0.f;
  const float scale = 0.223606797749979f;  // 20^-0.5

  for (int j = 0; j < 256; j++){
    float s = 0.f;
    #pragma unroll
    for (int d = 0; d < 20; d++) s = fmaf(q[d], ks[j][d], s);
    s *= scale;
    if (masked && rid[j] != myrid) s -= 100.0f;
    float m2 = fmaxf(m, s);
    if (m2 > m){
      float alpha = fexp(m - m2);
      l *= alpha;
      #pragma unroll
      for (int d = 0; d < 20; d++) acc[d] *= alpha;
      m = m2;
    }
    float p = fexp(s - m);
    l += p;
    #pragma unroll
    for (int d = 0; d < 20; d++) acc[d] = fmaf(p, vs[j][d], acc[d]);
  }
  float inv = 1.0f / l;
  float* op = out + (size_t)gidx*60 + head*20;
  #pragma unroll
  for (int d = 0; d < 20; d++) op[d] = acc[d]*inv;
}

// ---------------- last conv (60->12) fused with PixelShuffle(2) ------------
__global__ __launch_bounds__(256) void conv_out_kernel(
    const float* __restrict__ feat, const float* __restrict__ w,
    const float* __restrict__ b, float* __restrict__ out)
{
  int idx = blockIdx.x*256 + threadIdx.x;
  if (idx >= 2*3*256*256) return;
  int xq = idx & 255;
  int yq = (idx >> 8) & 255;
  int c  = (idx >> 16) % 3;
  int bq = idx / (3*65536);
  int co = c*4 + (yq & 1)*2 + (xq & 1);
  int hi = yq >> 1, wi = xq >> 1;
  float s = b[co];
  #pragma unroll
  for (int kh = 0; kh < 3; kh++){
    int hh = hi + kh - 1;
    if ((unsigned)hh > 127u) continue;
    #pragma unroll
    for (int kw = 0; kw < 3; kw++){
      int wwq = wi + kw - 1;
      if ((unsigned)wwq > 127u) continue;
      const float* fp = feat + (size_t)((bq*128 + hh)*128 + wwq)*60;
      const float* wp = w + ((size_t)co*60)*9 + kh*3 + kw;
      #pragma unroll
      for (int ci = 0; ci < 60; ci++)
        s = fmaf(fp[ci], wp[(size_t)ci*9], s);
    }
  }
  out[idx] = s;
}

// ---------------- launcher -------------------------------------------------
extern "C" void kernel_launch(void* const* d_in, const int* in_sizes, int n_in,
                              void* d_out, int out_size)
{
  const float* x      = (const float*)d_in[0];
  const float* conv_w = (const float*)d_in[1];
  const float* conv_b = (const float*)d_in[2];
  const float* ln1_g  = (const float*)d_in[3];
  const float* ln1_b  = (const float*)d_in[4];
  const float* qkv_w  = (const float*)d_in[5];
  const float* qkv_b  = (const float*)d_in[6];
  const float* proj_w = (const float*)d_in[7];
  const float* proj_b = (const float*)d_in[8];
  const float* ln2_g  = (const float*)d_in[9];
  const float* ln2_b  = (const float*)d_in[10];
  const float* fc1_w  = (const float*)d_in[11];
  const float* fc1_b  = (const float*)d_in[12];
  const float* fc2_w  = (const float*)d_in[13];
  const float* fc2_b  = (const float*)d_in[14];
  const float* last_w = (const float*)d_in[15];
  const float* last_b = (const float*)d_in[16];
  float* out = (float*)d_out;

  float *feat, *qkvb, *attnb, *mlpb;
  cudaGetSymbolAddress((void**)&feat,  g_feat);
  cudaGetSymbolAddress((void**)&qkvb,  g_qkv);
  cudaGetSymbolAddress((void**)&attnb, g_attn);
  cudaGetSymbolAddress((void**)&mlpb,  g_mlp);

  conv_in_kernel<<<(TOKENS*60 + 255)/256, 256>>>(x, conv_w, conv_b, feat);

  for (int l = 0; l < 36; l++){
    int i  = l % 6;
    int wi = i & 1;
    int wh = wi ? 8  : 32;
    int ww = wi ? 32 : 8;
    int shifted = (i % 4) >= 2;
    int sh = shifted ? (wi ? 4  : 16) : 0;
    int sw = shifted ? (wi ? 16 : 4 ) : 0;

    // LN1 + QKV:   [32768,60] x [60,180]
    gemm_kernel<60,true,false,false><<<dim3(512,3), 256>>>(
        feat, qkv_w + (size_t)l*60*180, qkv_b + (size_t)l*180,
        ln1_g + (size_t)l*60, ln1_b + (size_t)l*60, qkvb, 180);

    // window attention
    attn_kernel<<<dim3(128,3), 256>>>(qkvb, attnb, wh, ww, sh, sw, shifted);

    // proj + residual:  feat += attn @ [60,60]
    gemm_kernel<60,false,false,true><<<dim3(512,1), 256>>>(
        attnb, proj_w + (size_t)l*3600, proj_b + (size_t)l*60,
        nullptr, nullptr, feat, 60);

    // LN2 + FC1 + swish:  [32768,60] x [60,120]
    gemm_kernel<60,true,true,false><<<dim3(512,2), 256>>>(
        feat, fc1_w + (size_t)l*7200, fc1_b + (size_t)l*120,
        ln2_g + (size_t)l*60, ln2_b + (size_t)l*60, mlpb, 120);

    // FC2 + residual:  feat += mlp @ [120,60]
    gemm_kernel<120,false,false,true><<<dim3(512,1), 256>>>(
        mlpb, fc2_w + (size_t)l*7200, fc2_b + (size_t)l*60,
        nullptr, nullptr, feat, 60);
  }

  conv_out_kernel<<<(2*3*256*256 + 255)/256, 256>>>(feat, last_w, last_b, out);
}

// round 6
// speedup vs baseline: 1.4325x; 1.4325x over previous
#include <cuda_runtime.h>
#include <cstdint>
#include <cstddef>

#define TOKENS (2*128*128)

// ---------------- scratch (device globals; no allocation allowed) ----------
__device__ float g_feat[TOKENS*60];
__device__ float g_qkv [TOKENS*180];
__device__ float g_attn[TOKENS*60];

// ---------------- FFMA-only exp (avoids MUFU bottleneck) -------------------
__device__ __forceinline__ float fexp(float x){
  x = fminf(fmaxf(x, -87.0f), 87.0f);
  float t  = x * 1.4426950408889634f;       // x * log2(e)
  float kf = t + 12582912.0f;               // 1.5 * 2^23 round-to-nearest
  float i  = kf - 12582912.0f;              // integer part (exact float)
  float f  = t - i;                         // frac in [-0.5, 0.5]
  float p  = 1.3333558e-3f;                 // 2^f Taylor deg-5
  p = fmaf(p, f, 9.6181291e-3f);
  p = fmaf(p, f, 5.5504109e-2f);
  p = fmaf(p, f, 2.4022651e-1f);
  p = fmaf(p, f, 6.9314718e-1f);
  p = fmaf(p, f, 1.0f);
  int e = (int)i;
  return p * __int_as_float((e + 127) << 23);
}

__device__ __forceinline__ float frcp_nr(float y){
  float r = __int_as_float(0x7EF311C3u - __float_as_int(y));
  r = r * (2.0f - y * r);
  r = r * (2.0f - y * r);
  return r;
}

// ---------------- first conv: x[2,3,128,128] -> feat[2,128,128,60] ---------
__global__ __launch_bounds__(256) void conv_in_kernel(
    const float* __restrict__ x, const float* __restrict__ w,
    const float* __restrict__ b, float* __restrict__ feat)
{
  int idx = blockIdx.x*256 + threadIdx.x;
  if (idx >= TOKENS*60) return;
  int co = idx % 60;
  int t  = idx / 60;
  int wq = t & 127;
  int hq = (t >> 7) & 127;
  int bq = t >> 14;
  float s = b[co];
  #pragma unroll
  for (int kh = 0; kh < 3; kh++){
    int hh = hq + kh - 1;
    if ((unsigned)hh > 127u) continue;
    #pragma unroll
    for (int kw = 0; kw < 3; kw++){
      int wwq = wq + kw - 1;
      if ((unsigned)wwq > 127u) continue;
      const float* xp = x + (size_t)((bq*3)*128 + hh)*128 + wwq;
      #pragma unroll
      for (int ci = 0; ci < 3; ci++)
        s = fmaf(xp[(size_t)ci*128*128], w[((co*3+ci)*3+kh)*3+kw], s);
    }
  }
  feat[idx] = s;
}

// ---------------- GEMM: block 128(M) x 60(N), 240 threads, 8x4 tile --------
// X:[M,K] row-major, W:[K,Nfull], Out:[M,Nfull].  Xs stored transposed
// [k][m] with pad-129: conflict-free k-major a-loads AND column-walk LN.
template<int K, bool DOLN, bool RESID>
__global__ __launch_bounds__(240) void gemm_kernel(
    const float* __restrict__ X, const float* __restrict__ W,
    const float* __restrict__ bias,
    const float* __restrict__ lng, const float* __restrict__ lnb,
    float* __restrict__ Out, int Nfull)
{
  static_assert(!(DOLN && K != 60), "LN fusion only for K=60");
  __shared__ float Xs[60][129];
  __shared__ float Ws[60][60];
  __shared__ float lg[60], lb[60];
  const int m0  = blockIdx.x * 128;
  const int n0  = blockIdx.y * 60;
  const int tid = threadIdx.x;
  const int tx  = tid % 15;        // 0..14 -> n
  const int ty  = tid / 15;        // 0..15 -> m

  if (DOLN && tid < 60){ lg[tid] = lng[tid]; lb[tid] = lnb[tid]; }

  float acc[8][4];
  #pragma unroll
  for (int i = 0; i < 8; i++)
    #pragma unroll
    for (int j = 0; j < 4; j++) acc[i][j] = 0.f;

  for (int k0 = 0; k0 < K; k0 += 60){
    #pragma unroll
    for (int idx = tid; idx < 128*60; idx += 240){
      int m = idx / 60, k = idx - m*60;
      Xs[k][m] = X[(size_t)(m0+m)*K + k0 + k];
    }
    #pragma unroll
    for (int idx = tid; idx < 60*60; idx += 240){
      int k = idx / 60, n = idx - k*60;
      Ws[k][n] = W[(size_t)(k0+k)*Nfull + n0 + n];
    }
    __syncthreads();
    if (DOLN){
      if (tid < 128){
        float mu = 0.f;
        #pragma unroll
        for (int c = 0; c < 60; c++) mu += Xs[c][tid];
        mu *= (1.0f/60.0f);
        float var = 0.f;
        #pragma unroll
        for (int c = 0; c < 60; c++){ float d = Xs[c][tid]-mu; var = fmaf(d,d,var); }
        float rs = rsqrtf(var*(1.0f/60.0f) + 1e-5f);
        #pragma unroll
        for (int c = 0; c < 60; c++)
          Xs[c][tid] = (Xs[c][tid]-mu)*rs*lg[c] + lb[c];
      }
      __syncthreads();
    }
    #pragma unroll 12
    for (int k = 0; k < 60; k++){
      float4 b4 = *reinterpret_cast<const float4*>(&Ws[k][tx*4]);
      float a[8];
      #pragma unroll
      for (int i = 0; i < 8; i++) a[i] = Xs[k][ty*8+i];
      #pragma unroll
      for (int i = 0; i < 8; i++){
        acc[i][0] = fmaf(a[i], b4.x, acc[i][0]);
        acc[i][1] = fmaf(a[i], b4.y, acc[i][1]);
        acc[i][2] = fmaf(a[i], b4.z, acc[i][2]);
        acc[i][3] = fmaf(a[i], b4.w, acc[i][3]);
      }
    }
    __syncthreads();
  }

  float4 bb = *reinterpret_cast<const float4*>(&bias[n0 + tx*4]);
  #pragma unroll
  for (int i = 0; i < 8; i++){
    size_t o = (size_t)(m0 + ty*8 + i) * Nfull + n0 + tx*4;
    float v0 = acc[i][0] + bb.x;
    float v1 = acc[i][1] + bb.y;
    float v2 = acc[i][2] + bb.z;
    float v3 = acc[i][3] + bb.w;
    if (RESID){
      float4 old = *reinterpret_cast<const float4*>(&Out[o]);
      v0 += old.x; v1 += old.y; v2 += old.z; v3 += old.w;
    }
    float4 res = make_float4(v0, v1, v2, v3);
    *reinterpret_cast<float4*>(&Out[o]) = res;
  }
}

// ---------------- fused MLP: feat += swish(LN2(feat)@W1+b1)@W2+b2 ----------
// 128-row tile, 240 threads.  Stage A: acc[8][8] (n=120), swish.  Hidden is
// staged transposed through smem (union with dead Xs/Ws1), then stage B
// contracts k=120 into acc2[8][4] and residual-adds into feat.
#define FMLP_SMEM_BYTES (22680*4)
__global__ __launch_bounds__(240, 2) void fused_mlp_kernel(
    float* __restrict__ feat,
    const float* __restrict__ W1, const float* __restrict__ b1,
    const float* __restrict__ W2, const float* __restrict__ b2,
    const float* __restrict__ lng, const float* __restrict__ lnb)
{
  extern __shared__ float pool[];
  float* Xs  = pool;           // [60][129]   7740 floats
  float* Ws1 = pool + 7740;    // [60][120]   7200 floats
  float* hs  = pool;           // [120][129] 15480 floats (union after stage A)
  float* Ws2 = pool + 15480;   // [120][60]   7200 floats
  __shared__ float lg[60], lb[60];

  const int m0  = blockIdx.x * 128;
  const int tid = threadIdx.x;
  const int tx  = tid % 15;    // n-group
  const int ty  = tid / 15;    // m-group

  if (tid < 60){ lg[tid] = lng[tid]; lb[tid] = lnb[tid]; }

  #pragma unroll
  for (int idx = tid; idx < 128*60; idx += 240){
    int m = idx / 60, k = idx - m*60;
    Xs[k*129 + m] = feat[(size_t)(m0+m)*60 + k];
  }
  #pragma unroll
  for (int idx = tid; idx < 60*120; idx += 240) Ws1[idx] = W1[idx];
  #pragma unroll
  for (int idx = tid; idx < 120*60; idx += 240) Ws2[idx] = W2[idx];
  __syncthreads();

  if (tid < 128){
    float mu = 0.f;
    #pragma unroll
    for (int c = 0; c < 60; c++) mu += Xs[c*129 + tid];
    mu *= (1.0f/60.0f);
    float var = 0.f;
    #pragma unroll
    for (int c = 0; c < 60; c++){ float d = Xs[c*129 + tid]-mu; var = fmaf(d,d,var); }
    float rs = rsqrtf(var*(1.0f/60.0f) + 1e-5f);
    #pragma unroll
    for (int c = 0; c < 60; c++)
      Xs[c*129 + tid] = (Xs[c*129 + tid]-mu)*rs*lg[c] + lb[c];
  }
  __syncthreads();

  // stage A: h = LN(X) @ W1  (128 x 120)
  float acc[8][8];
  #pragma unroll
  for (int i = 0; i < 8; i++)
    #pragma unroll
    for (int j = 0; j < 8; j++) acc[i][j] = 0.f;

  #pragma unroll 4
  for (int k = 0; k < 60; k++){
    float4 bA = *reinterpret_cast<const float4*>(&Ws1[k*120 + tx*8]);
    float4 bB = *reinterpret_cast<const float4*>(&Ws1[k*120 + tx*8 + 4]);
    float a[8];
    #pragma unroll
    for (int i = 0; i < 8; i++) a[i] = Xs[k*129 + ty*8 + i];
    #pragma unroll
    for (int i = 0; i < 8; i++){
      acc[i][0] = fmaf(a[i], bA.x, acc[i][0]);
      acc[i][1] = fmaf(a[i], bA.y, acc[i][1]);
      acc[i][2] = fmaf(a[i], bA.z, acc[i][2]);
      acc[i][3] = fmaf(a[i], bA.w, acc[i][3]);
      acc[i][4] = fmaf(a[i], bB.x, acc[i][4]);
      acc[i][5] = fmaf(a[i], bB.y, acc[i][5]);
      acc[i][6] = fmaf(a[i], bB.z, acc[i][6]);
      acc[i][7] = fmaf(a[i], bB.w, acc[i][7]);
    }
  }

  // bias + swish
  float4 b1a = *reinterpret_cast<const float4*>(&b1[tx*8]);
  float4 b1b = *reinterpret_cast<const float4*>(&b1[tx*8 + 4]);
  float bb1[8] = {b1a.x,b1a.y,b1a.z,b1a.w,b1b.x,b1b.y,b1b.z,b1b.w};
  #pragma unroll
  for (int i = 0; i < 8; i++)
    #pragma unroll
    for (int j = 0; j < 8; j++){
      float v = acc[i][j] + bb1[j];
      acc[i][j] = v * frcp_nr(1.0f + fexp(-v));
    }

  __syncthreads();   // everyone done reading Xs/Ws1 before hs overwrite

  // stage hidden transposed: hs[n][m]
  #pragma unroll
  for (int j = 0; j < 8; j++)
    #pragma unroll
    for (int i = 0; i < 8; i++)
      hs[(tx*8 + j)*129 + ty*8 + i] = acc[i][j];
  __syncthreads();

  // stage B: out = h @ W2  (contract k = 120)
  float acc2[8][4];
  #pragma unroll
  for (int i = 0; i < 8; i++)
    #pragma unroll
    for (int j = 0; j < 4; j++) acc2[i][j] = 0.f;

  #pragma unroll 6
  for (int k = 0; k < 120; k++){
    float4 b4 = *reinterpret_cast<const float4*>(&Ws2[k*60 + tx*4]);
    float a[8];
    #pragma unroll
    for (int i = 0; i < 8; i++) a[i] = hs[k*129 + ty*8 + i];
    #pragma unroll
    for (int i = 0; i < 8; i++){
      acc2[i][0] = fmaf(a[i], b4.x, acc2[i][0]);
      acc2[i][1] = fmaf(a[i], b4.y, acc2[i][1]);
      acc2[i][2] = fmaf(a[i], b4.z, acc2[i][2]);
      acc2[i][3] = fmaf(a[i], b4.w, acc2[i][3]);
    }
  }

  float4 bb2 = *reinterpret_cast<const float4*>(&b2[tx*4]);
  #pragma unroll
  for (int i = 0; i < 8; i++){
    size_t o = (size_t)(m0 + ty*8 + i) * 60 + tx*4;
    float4 old = *reinterpret_cast<const float4*>(&feat[o]);
    float4 res = make_float4(old.x + acc2[i][0] + bb2.x,
                             old.y + acc2[i][1] + bb2.y,
                             old.z + acc2[i][2] + bb2.z,
                             old.w + acc2[i][3] + bb2.w);
    *reinterpret_cast<float4*>(&feat[o]) = res;
  }
}

// ---------------- windowed attention (flash-style, float4 K/V) -------------
__global__ __launch_bounds__(256) void attn_kernel(
    const float* __restrict__ qkv, float* __restrict__ out,
    int wh, int ww, int sh, int sw, int masked)
{
  __shared__ float4 ks4[256][5];
  __shared__ float4 vs4[256][5];
  __shared__ int    rid[256];
  const int win  = blockIdx.x;
  const int head = blockIdx.y;
  const int nWc = 128 / ww;
  const int nHc = 128 / wh;
  const int b   = win / (nHc*nWc);
  const int rem = win % (nHc*nWc);
  const int ih  = rem / nWc, iw = rem % nWc;
  const int n   = threadIdx.x;
  const int r   = n / ww, col = n % ww;
  const int h   = ih*wh + r, w = iw*ww + col;
  const int gh  = (h + sh) & 127, gw = (w + sw) & 127;
  const int gidx = (b*128 + gh)*128 + gw;
  const float4* bp4 = reinterpret_cast<const float4*>(qkv + (size_t)gidx*180 + head*20);

  const float scale = 0.223606797749979f;  // 20^-0.5
  float4 q4[5];
  #pragma unroll
  for (int d = 0; d < 5; d++){
    float4 qv = bp4[d];
    qv.x *= scale; qv.y *= scale; qv.z *= scale; qv.w *= scale;
    q4[d]     = qv;
    ks4[n][d] = bp4[15+d];
    vs4[n][d] = bp4[30+d];
  }
  int rh = (h < 128-wh) ? 0 : ((h < 128-sh) ? 1 : 2);
  int rw = (w < 128-ww) ? 0 : ((w < 128-sw) ? 1 : 2);
  rid[n] = rh*3 + rw;
  __syncthreads();

  const int myrid = rid[n];
  float m = -3.0e38f, l = 0.f;
  float4 a4[5];
  #pragma unroll
  for (int d = 0; d < 5; d++) a4[d] = make_float4(0.f,0.f,0.f,0.f);

  for (int j = 0; j < 256; j++){
    float s = 0.f;
    #pragma unroll
    for (int d = 0; d < 5; d++){
      float4 kk = ks4[j][d];
      s = fmaf(q4[d].x, kk.x, s);
      s = fmaf(q4[d].y, kk.y, s);
      s = fmaf(q4[d].z, kk.z, s);
      s = fmaf(q4[d].w, kk.w, s);
    }
    if (masked && rid[j] != myrid) s -= 100.0f;
    float m2 = fmaxf(m, s);
    if (m2 > m){
      float alpha = fexp(m - m2);
      l *= alpha;
      #pragma unroll
      for (int d = 0; d < 5; d++){
        a4[d].x *= alpha; a4[d].y *= alpha; a4[d].z *= alpha; a4[d].w *= alpha;
      }
      m = m2;
    }
    float p = fexp(s - m);
    l += p;
    #pragma unroll
    for (int d = 0; d < 5; d++){
      float4 vv = vs4[j][d];
      a4[d].x = fmaf(p, vv.x, a4[d].x);
      a4[d].y = fmaf(p, vv.y, a4[d].y);
      a4[d].z = fmaf(p, vv.z, a4[d].z);
      a4[d].w = fmaf(p, vv.w, a4[d].w);
    }
  }
  float inv = 1.0f / l;
  float4* op4 = reinterpret_cast<float4*>(out + (size_t)gidx*60 + head*20);
  #pragma unroll
  for (int d = 0; d < 5; d++){
    float4 v = a4[d];
    v.x *= inv; v.y *= inv; v.z *= inv; v.w *= inv;
    op4[d] = v;
  }
}

// ---------------- last conv (60->12) fused with PixelShuffle(2) ------------
__global__ __launch_bounds__(256) void conv_out_kernel(
    const float* __restrict__ feat, const float* __restrict__ w,
    const float* __restrict__ b, float* __restrict__ out)
{
  int idx = blockIdx.x*256 + threadIdx.x;
  if (idx >= 2*3*256*256) return;
  int xq = idx & 255;
  int yq = (idx >> 8) & 255;
  int c  = (idx >> 16) % 3;
  int bq = idx / (3*65536);
  int co = c*4 + (yq & 1)*2 + (xq & 1);
  int hi = yq >> 1, wi = xq >> 1;
  float s = b[co];
  #pragma unroll
  for (int kh = 0; kh < 3; kh++){
    int hh = hi + kh - 1;
    if ((unsigned)hh > 127u) continue;
    #pragma unroll
    for (int kw = 0; kw < 3; kw++){
      int wwq = wi + kw - 1;
      if ((unsigned)wwq > 127u) continue;
      const float* fp = feat + (size_t)((bq*128 + hh)*128 + wwq)*60;
      const float* wp = w + ((size_t)co*60)*9 + kh*3 + kw;
      #pragma unroll
      for (int ci = 0; ci < 60; ci++)
        s = fmaf(fp[ci], wp[(size_t)ci*9], s);
    }
  }
  out[idx] = s;
}

// ---------------- launcher -------------------------------------------------
extern "C" void kernel_launch(void* const* d_in, const int* in_sizes, int n_in,
                              void* d_out, int out_size)
{
  const float* x      = (const float*)d_in[0];
  const float* conv_w = (const float*)d_in[1];
  const float* conv_b = (const float*)d_in[2];
  const float* ln1_g  = (const float*)d_in[3];
  const float* ln1_b  = (const float*)d_in[4];
  const float* qkv_w  = (const float*)d_in[5];
  const float* qkv_b  = (const float*)d_in[6];
  const float* proj_w = (const float*)d_in[7];
  const float* proj_b = (const float*)d_in[8];
  const float* ln2_g  = (const float*)d_in[9];
  const float* ln2_b  = (const float*)d_in[10];
  const float* fc1_w  = (const float*)d_in[11];
  const float* fc1_b  = (const float*)d_in[12];
  const float* fc2_w  = (const float*)d_in[13];
  const float* fc2_b  = (const float*)d_in[14];
  const float* last_w = (const float*)d_in[15];
  const float* last_b = (const float*)d_in[16];
  float* out = (float*)d_out;

  // persistent per-function attribute; set on the (pre-capture) correctness
  // call, persists into capture
  cudaFuncSetAttribute(fused_mlp_kernel,
                       cudaFuncAttributeMaxDynamicSharedMemorySize,
                       FMLP_SMEM_BYTES);

  float *feat, *qkvb, *attnb;
  cudaGetSymbolAddress((void**)&feat,  g_feat);
  cudaGetSymbolAddress((void**)&qkvb,  g_qkv);
  cudaGetSymbolAddress((void**)&attnb, g_attn);

  conv_in_kernel<<<(TOKENS*60 + 255)/256, 256>>>(x, conv_w, conv_b, feat);

  for (int l = 0; l < 36; l++){
    int i  = l % 6;
    int wi = i & 1;
    int wh = wi ? 8  : 32;
    int ww = wi ? 32 : 8;
    int shifted = (i % 4) >= 2;
    int sh = shifted ? (wi ? 4  : 16) : 0;
    int sw = shifted ? (wi ? 16 : 4 ) : 0;

    // LN1 + QKV:   [32768,60] x [60,180]
    gemm_kernel<60,true,false><<<dim3(256,3), 240>>>(
        feat, qkv_w + (size_t)l*60*180, qkv_b + (size_t)l*180,
        ln1_g + (size_t)l*60, ln1_b + (size_t)l*60, qkvb, 180);

    // window attention
    attn_kernel<<<dim3(128,3), 256>>>(qkvb, attnb, wh, ww, sh, sw, shifted);

    // proj + residual:  feat += attn @ [60,60]
    gemm_kernel<60,false,true><<<dim3(256,1), 240>>>(
        attnb, proj_w + (size_t)l*3600, proj_b + (size_t)l*60,
        nullptr, nullptr, feat, 60);

    // fused MLP: feat += swish(LN2(feat)@W1+b1)@W2+b2
    fused_mlp_kernel<<<256, 240, FMLP_SMEM_BYTES>>>(
        feat, fc1_w + (size_t)l*7200, fc1_b + (size_t)l*120,
        fc2_w + (size_t)l*7200, fc2_b + (size_t)l*60,
        ln2_g + (size_t)l*60, ln2_b + (size_t)l*60);
  }

  conv_out_kernel<<<(2*3*256*256 + 255)/256, 256>>>(feat, last_w, last_b, out);
}